// round 1
// baseline (speedup 1.0000x reference)
#include <cuda_runtime.h>
#include <cuda_bf16.h>

// WaveletTransformLayer: x (B=128, T=2048, F=32) f32.
// Pyramid of moving averages w=[2,4,8]; outputs per (b,f):
//   d1 (2047) | d2 (2044) | d3 (2037) | ma3 (2037)  -> 8165 per feature, /T.
// Nested box filters collapse to small FIR taps:
//   ma1 = box2 ; ma2 = [1,2,2,2,1]/8 ; ma3 = [1,3,5,7,8,8,8,8,7,5,3,1]/64
// Pure memory-bound problem: ~33.5 MB read, ~133.8 MB write.

#define T_LEN   2048
#define F_DIM   32
#define TT      256           // t-tile per block
#define HALO    12            // need x[t .. t+11]
#define PITCH   33            // smem pitch (bank-conflict-free for stride-32 access)
#define OUT_PER_F 8165        // 2047 + 2044 + 2037 + 2037
#define SEG1    2047
#define SEG2    4091          // 2047 + 2044
#define SEG3    6128          // + 2037

__global__ __launch_bounds__(256, 1)
void wavelet_kernel(const float* __restrict__ x, float* __restrict__ out) {
    __shared__ float xs[(TT + HALO) * PITCH];

    const int tile = blockIdx.x;          // 0..7
    const int b    = blockIdx.y;          // 0..127
    const int t0   = tile * TT;
    const int tid  = threadIdx.x;         // 0..255

    // ---- Load (TT+HALO) x F slab: contiguous in global memory ----
    const float* gsrc = x + (size_t)b * (T_LEN * F_DIM) + (size_t)t0 * F_DIM;
    const int total = (TT + HALO) * F_DIM;   // 268*32 = 8576
    #pragma unroll 4
    for (int i = tid; i < total; i += 256) {
        int tt = i >> 5;          // local t
        int f  = i & 31;
        int tg = t0 + tt;
        xs[tt * PITCH + f] = (tg < T_LEN) ? gsrc[i] : 0.0f;
    }
    __syncthreads();

    // ---- Compute: thread = t_local, loop over f (stores warp-contiguous in t) ----
    const int t  = tid;
    const int tg = t0 + t;
    float* outb = out + (size_t)b * (F_DIM * OUT_PER_F);

    const float inv = 1.0f / 2048.0f;     // 1/T
    const float inv2  = inv * 0.5f;
    const float inv8  = inv * 0.125f;
    const float inv64 = inv * 0.015625f;

    const bool w1 = (tg < 2047);
    const bool w2 = (tg < 2044);
    const bool w3 = (tg < 2037);

    #pragma unroll 4
    for (int f = 0; f < F_DIM; ++f) {
        const float* s = xs + t * PITCH + f;
        float x0  = s[0 * PITCH];
        float x1  = s[1 * PITCH];
        float x2  = s[2 * PITCH];
        float x3  = s[3 * PITCH];
        float x4  = s[4 * PITCH];
        float x5  = s[5 * PITCH];
        float x6  = s[6 * PITCH];
        float x7  = s[7 * PITCH];
        float x8  = s[8 * PITCH];
        float x9  = s[9 * PITCH];
        float x10 = s[10 * PITCH];
        float x11 = s[11 * PITCH];

        // d1 = (x1 - x0)/2
        float d1 = (x1 - x0) * inv2;

        // ma2[t] = (x0 + x4 + 2(x1+x2+x3)) / 8
        float m2a = x0 + x4 + 2.0f * (x1 + x2 + x3);
        // d2 = (x3+x4)/2 - ma2[t]
        float d2 = (x3 + x4) * inv2 - m2a * inv8;

        // ma2[t+7] = (x7 + x11 + 2(x8+x9+x10)) / 8
        float m2b = x7 + x11 + 2.0f * (x8 + x9 + x10);
        // ma3[t]: taps [1,3,5,7,8,8,8,8,7,5,3,1]/64
        float m3 = (x0 + x11)
                 + 3.0f * (x1 + x10)
                 + 5.0f * (x2 + x9)
                 + 7.0f * (x3 + x8)
                 + 8.0f * (x4 + x5 + x6 + x7);
        float d3  = m2b * inv8 - m3 * inv64;
        float ma3 = m3 * inv64;

        float* of = outb + (size_t)f * OUT_PER_F;
        if (w1) of[tg]        = d1;
        if (w2) of[SEG1 + tg] = d2;
        if (w3) {
            of[SEG2 + tg] = d3;
            of[SEG3 + tg] = ma3;
        }
    }
}

extern "C" void kernel_launch(void* const* d_in, const int* in_sizes, int n_in,
                              void* d_out, int out_size) {
    const float* x = (const float*)d_in[0];
    float* out = (float*)d_out;
    dim3 grid(T_LEN / TT, 128);   // 8 x 128 = 1024 blocks
    wavelet_kernel<<<grid, 256>>>(x, out);
}

// round 2
// speedup vs baseline: 1.0071x; 1.0071x over previous
#include <cuda_runtime.h>
#include <cuda_bf16.h>

// WaveletTransformLayer: x (B=128, T=2048, F=32) f32.
// Outputs per (b,f): d1 (2047) | d2 (2044) | d3 (2037) | ma3 (2037), each /T.
// Collapsed FIR taps:
//   ma1 = box2 ; ma2 = [1,2,2,2,1]/8 ; ma3 = [1,3,5,7,8,8,8,8,7,5,3,1]/64
//   d1[t] = (x[t+1]-x[t])/2
//   d2[t] = (x[t+3]+x[t+4])/2 - ma2[t]
//   d3[t] = ma2[t+7] - ma3[t]
// Memory-bound: ~34 MB read, ~134 MB write. HBM floor ~21 us.

#define T_LEN   2048
#define F_DIM   32
#define TT      128          // t-tile per block
#define HALO    12           // window reaches x[t+11]
#define LOADT   (TT + HALO)  // 140
#define PITCH   36           // t-major pitch: STS.128 & LDS.64 conflict-free
#define OUT_PER_F 8165       // 2047 + 2044 + 2037 + 2037
#define SEG1    2047
#define SEG2    4091
#define SEG3    6128
#define LIM1    2047
#define LIM2    2044
#define LIM3    2037

__global__ __launch_bounds__(128, 8)
void wavelet_kernel(const float* __restrict__ x, float* __restrict__ out) {
    __shared__ float xs[LOADT * PITCH];   // 140*36*4 = 20160 B

    const int tile = blockIdx.x;          // 0..15
    const int b    = blockIdx.y;          // 0..127
    const int t0   = tile * TT;
    const int tid  = threadIdx.x;         // 0..127

    // ---- Load (LOADT x 32f) slab: LDG.128 -> STS.128 (conflict-free) ----
    // Global is t-major with f contiguous: vec4 i covers (tt = i>>3, f = 4*(i&7)..+3)
    const float4* gsrc = (const float4*)(x + (size_t)b * (T_LEN * F_DIM)
                                           + (size_t)t0 * F_DIM);
    #pragma unroll
    for (int k = 0; k < 9; ++k) {
        int i = tid + k * 128;
        if (i < LOADT * 8) {              // 1120 vec4s
            int tt = i >> 3;
            int f4 = (i & 7) << 2;
            float4 v = make_float4(0.f, 0.f, 0.f, 0.f);
            if (t0 + tt < T_LEN) v = gsrc[i];
            *(float4*)&xs[tt * PITCH + f4] = v;
        }
    }
    __syncthreads();

    // ---- Compute: thread = t (lane-contiguous -> coalesced scalar stores),
    //      two features at a time via LDS.64 ----
    const int t  = tid;
    const int tg = t0 + t;
    float* outb = out + (size_t)b * (F_DIM * OUT_PER_F);

    const float inv   = 1.0f / 2048.0f;
    const float inv2  = inv * 0.5f;
    const float inv8  = inv * 0.125f;
    const float inv64 = inv * 0.015625f;

    const bool full = (t0 + TT <= LIM3);  // tiles 0..14: no store predication
    const bool w1 = (tg < LIM1);
    const bool w2 = (tg < LIM2);
    const bool w3 = (tg < LIM3);

    #pragma unroll 4
    for (int fp = 0; fp < F_DIM / 2; ++fp) {
        const int f = fp << 1;
        float2 w[12];
        #pragma unroll
        for (int j = 0; j < 12; ++j)
            w[j] = *(const float2*)&xs[(t + j) * PITCH + f];

        // ---- feature f (x components) ----
        float d1a = (w[1].x - w[0].x) * inv2;
        float m2a = w[0].x + w[4].x + 2.0f * (w[1].x + w[2].x + w[3].x);
        float d2a = (w[3].x + w[4].x) * inv2 - m2a * inv8;
        float m2s = w[7].x + w[11].x + 2.0f * (w[8].x + w[9].x + w[10].x);
        float m3a = (w[0].x + w[11].x)
                  + 3.0f * (w[1].x + w[10].x)
                  + 5.0f * (w[2].x + w[9].x)
                  + 7.0f * (w[3].x + w[8].x)
                  + 8.0f * (w[4].x + w[5].x + w[6].x + w[7].x);
        float d3a  = m2s * inv8 - m3a * inv64;
        float ma3a = m3a * inv64;

        // ---- feature f+1 (y components) ----
        float d1b = (w[1].y - w[0].y) * inv2;
        float m2b = w[0].y + w[4].y + 2.0f * (w[1].y + w[2].y + w[3].y);
        float d2b = (w[3].y + w[4].y) * inv2 - m2b * inv8;
        float m2t = w[7].y + w[11].y + 2.0f * (w[8].y + w[9].y + w[10].y);
        float m3b = (w[0].y + w[11].y)
                  + 3.0f * (w[1].y + w[10].y)
                  + 5.0f * (w[2].y + w[9].y)
                  + 7.0f * (w[3].y + w[8].y)
                  + 8.0f * (w[4].y + w[5].y + w[6].y + w[7].y);
        float d3b  = m2t * inv8 - m3b * inv64;
        float ma3b = m3b * inv64;

        float* of0 = outb + (size_t)f * OUT_PER_F;
        float* of1 = of0 + OUT_PER_F;

        if (full) {
            of0[tg]        = d1a;   of1[tg]        = d1b;
            of0[SEG1 + tg] = d2a;   of1[SEG1 + tg] = d2b;
            of0[SEG2 + tg] = d3a;   of1[SEG2 + tg] = d3b;
            of0[SEG3 + tg] = ma3a;  of1[SEG3 + tg] = ma3b;
        } else {
            if (w1) { of0[tg]        = d1a;   of1[tg]        = d1b;  }
            if (w2) { of0[SEG1 + tg] = d2a;   of1[SEG1 + tg] = d2b;  }
            if (w3) {
                of0[SEG2 + tg] = d3a;   of1[SEG2 + tg] = d3b;
                of0[SEG3 + tg] = ma3a;  of1[SEG3 + tg] = ma3b;
            }
        }
    }
}

extern "C" void kernel_launch(void* const* d_in, const int* in_sizes, int n_in,
                              void* d_out, int out_size) {
    const float* x = (const float*)d_in[0];
    float* out = (float*)d_out;
    dim3 grid(T_LEN / TT, 128);   // 16 x 128 = 2048 blocks
    wavelet_kernel<<<grid, 128>>>(x, out);
}

// round 3
// speedup vs baseline: 1.0143x; 1.0072x over previous
#include <cuda_runtime.h>
#include <cuda_bf16.h>

// WaveletTransformLayer: x (B=128, T=2048, F=32) f32.
// Outputs per (b,f): d1 (2047) | d2 (2044) | d3 (2037) | ma3 (2037), each /T.
// Collapsed FIR taps:
//   ma1 = box2 ; ma2 = [1,2,2,2,1]/8 ; ma3 = [1,3,5,7,8,8,8,8,7,5,3,1]/64
//   d1[t] = (x[t+1]-x[t])/2
//   d2[t] = (x[t+3]+x[t+4])/2 - ma2[t]
//   d3[t] = ma2[t+7] - ma3[t]
// Memory-bound: ~34 MB read, ~134 MB write. HBM floor ~21 us.
//
// PITCH=34: LDS.64 at lane-stride 34 floats -> bank-pair (t + f/2) mod 16,
// distinct per 16-lane phase => conflict-free. (PITCH=36 was 2-way conflicted.)
// 136B row stride is only 8B-aligned, so smem fill uses STS.64 (LDG.128 kept).

#define T_LEN   2048
#define F_DIM   32
#define TT      128          // t-tile per block
#define HALO    12           // window reaches x[t+11]
#define LOADT   (TT + HALO)  // 140
#define PITCH   34
#define OUT_PER_F 8165       // 2047 + 2044 + 2037 + 2037
#define SEG1    2047
#define SEG2    4091
#define SEG3    6128
#define LIM1    2047
#define LIM2    2044
#define LIM3    2037

__global__ __launch_bounds__(128, 8)
void wavelet_kernel(const float* __restrict__ x, float* __restrict__ out) {
    __shared__ float xs[LOADT * PITCH];   // 140*34*4 = 19040 B

    const int tile = blockIdx.x;          // 0..15
    const int b    = blockIdx.y;          // 0..127
    const int t0   = tile * TT;
    const int tid  = threadIdx.x;         // 0..127

    // ---- Load (LOADT x 32f) slab: LDG.128 -> 2x STS.64 (conflict-free) ----
    const float4* gsrc = (const float4*)(x + (size_t)b * (T_LEN * F_DIM)
                                           + (size_t)t0 * F_DIM);
    #pragma unroll
    for (int k = 0; k < 9; ++k) {
        int i = tid + k * 128;
        if (i < LOADT * 8) {              // 1120 vec4s
            int tt = i >> 3;
            int f4 = (i & 7) << 2;
            float4 v = make_float4(0.f, 0.f, 0.f, 0.f);
            if (t0 + tt < T_LEN) v = gsrc[i];
            float* dst = &xs[tt * PITCH + f4];
            *(float2*)(dst)     = make_float2(v.x, v.y);
            *(float2*)(dst + 2) = make_float2(v.z, v.w);
        }
    }
    __syncthreads();

    // ---- Compute: thread = t (lane-contiguous -> coalesced scalar stores),
    //      two features at a time via conflict-free LDS.64 ----
    const int t  = tid;
    const int tg = t0 + t;
    float* outb = out + (size_t)b * (F_DIM * OUT_PER_F);

    const float inv   = 1.0f / 2048.0f;
    const float inv2  = inv * 0.5f;
    const float inv8  = inv * 0.125f;
    const float inv64 = inv * 0.015625f;

    const bool full = (t0 + TT <= LIM3);  // tiles 0..14: no store predication
    const bool w1 = (tg < LIM1);
    const bool w2 = (tg < LIM2);
    const bool w3 = (tg < LIM3);

    #pragma unroll 4
    for (int fp = 0; fp < F_DIM / 2; ++fp) {
        const int f = fp << 1;
        float2 w[12];
        #pragma unroll
        for (int j = 0; j < 12; ++j)
            w[j] = *(const float2*)&xs[(t + j) * PITCH + f];

        // ---- feature f (x components) ----
        float d1a = (w[1].x - w[0].x) * inv2;
        float m2a = w[0].x + w[4].x + 2.0f * (w[1].x + w[2].x + w[3].x);
        float d2a = (w[3].x + w[4].x) * inv2 - m2a * inv8;
        float m2s = w[7].x + w[11].x + 2.0f * (w[8].x + w[9].x + w[10].x);
        float m3a = (w[0].x + w[11].x)
                  + 3.0f * (w[1].x + w[10].x)
                  + 5.0f * (w[2].x + w[9].x)
                  + 7.0f * (w[3].x + w[8].x)
                  + 8.0f * (w[4].x + w[5].x + w[6].x + w[7].x);
        float d3a  = m2s * inv8 - m3a * inv64;
        float ma3a = m3a * inv64;

        // ---- feature f+1 (y components) ----
        float d1b = (w[1].y - w[0].y) * inv2;
        float m2b = w[0].y + w[4].y + 2.0f * (w[1].y + w[2].y + w[3].y);
        float d2b = (w[3].y + w[4].y) * inv2 - m2b * inv8;
        float m2t = w[7].y + w[11].y + 2.0f * (w[8].y + w[9].y + w[10].y);
        float m3b = (w[0].y + w[11].y)
                  + 3.0f * (w[1].y + w[10].y)
                  + 5.0f * (w[2].y + w[9].y)
                  + 7.0f * (w[3].y + w[8].y)
                  + 8.0f * (w[4].y + w[5].y + w[6].y + w[7].y);
        float d3b  = m2t * inv8 - m3b * inv64;
        float ma3b = m3b * inv64;

        float* of0 = outb + (size_t)f * OUT_PER_F;
        float* of1 = of0 + OUT_PER_F;

        if (full) {
            of0[tg]        = d1a;   of1[tg]        = d1b;
            of0[SEG1 + tg] = d2a;   of1[SEG1 + tg] = d2b;
            of0[SEG2 + tg] = d3a;   of1[SEG2 + tg] = d3b;
            of0[SEG3 + tg] = ma3a;  of1[SEG3 + tg] = ma3b;
        } else {
            if (w1) { of0[tg]        = d1a;   of1[tg]        = d1b;  }
            if (w2) { of0[SEG1 + tg] = d2a;   of1[SEG1 + tg] = d2b;  }
            if (w3) {
                of0[SEG2 + tg] = d3a;   of1[SEG2 + tg] = d3b;
                of0[SEG3 + tg] = ma3a;  of1[SEG3 + tg] = ma3b;
            }
        }
    }
}

extern "C" void kernel_launch(void* const* d_in, const int* in_sizes, int n_in,
                              void* d_out, int out_size) {
    const float* x = (const float*)d_in[0];
    float* out = (float*)d_out;
    dim3 grid(T_LEN / TT, 128);   // 16 x 128 = 2048 blocks
    wavelet_kernel<<<grid, 128>>>(x, out);
}